// round 8
// baseline (speedup 1.0000x reference)
#include <cuda_runtime.h>
#include <cstdint>

#define NPTS 2048
#define BATCH 8
#define KNN 20
#define NEGINF __int_as_float(0xff800000)
#define POSINF __int_as_float(0x7f800000)

typedef unsigned long long u64;

// ---------------- static device scratch (no allocation allowed) ----------------
__device__ int   d_idx[BATCH * NPTS * KNN];
__device__ float d_xx[BATCH * NPTS];
__device__ float d_x1[BATCH * NPTS * 64];
__device__ float d_x2[BATCH * NPTS * 64];
__device__ float d_x3[BATCH * NPTS * 128];
__device__ float d_x4[BATCH * NPTS * 256];
// packed edge-conv weights: diff part and center part, u64 = {W[o][2c], W[o][2c+1]}
__device__ u64  d_Wp1d[2 * 64],    d_Wp1c[2 * 64];      // C=3 -> Cp=4
__device__ u64  d_Wp2d[32 * 64],   d_Wp2c[32 * 64];     // C=64
__device__ u64  d_Wp3d[32 * 128],  d_Wp3c[32 * 128];    // C=64
__device__ u64  d_Wp4d[64 * 256],  d_Wp4c[64 * 256];    // C=128
__device__ float d_W5t[512 * 512];
__device__ float d_h5[BATCH * 512];

// ---------------- f32x2 helpers ----------------
__device__ __forceinline__ u64 fma2(u64 a, u64 b, u64 c) {
    u64 d;
    asm("fma.rn.f32x2 %0, %1, %2, %3;" : "=l"(d) : "l"(a), "l"(b), "l"(c));
    return d;
}
__device__ __forceinline__ u64 pack2(float lo, float hi) {
    u64 d;
    asm("mov.b64 %0, {%1, %2};" : "=l"(d) : "f"(lo), "f"(hi));
    return d;
}
__device__ __forceinline__ float2 unpack2(u64 v) {
    float2 r;
    asm("mov.b64 {%0, %1}, %2;" : "=f"(r.x), "=f"(r.y) : "l"(v));
    return r;
}

__device__ __forceinline__ void atomicMaxFloat(float* addr, float v) {
    if (v >= 0.f) atomicMax((int*)addr, __float_as_int(v));
    else          atomicMin((unsigned int*)addr, __float_as_uint(v));
}

// ---------------- pack edge-conv weights: W is (O, 2C) row-major ----------------
__global__ void pack_kernel(const float* __restrict__ W, u64* __restrict__ Wpd,
                            u64* __restrict__ Wpc, int O, int C, int Cp) {
    int i = blockIdx.x * 256 + threadIdx.x;
    int total = (Cp / 2) * O;
    if (i >= total) return;
    int c2 = i / O, o = i - c2 * O;
    int c0 = 2 * c2, c1 = 2 * c2 + 1;
    const float* row = W + (size_t)o * 2 * C;
    float a0 = (c0 < C) ? row[c0] : 0.f;
    float a1 = (c1 < C) ? row[c1] : 0.f;
    Wpd[c2 * O + o] = pack2(a0, a1);
    float e0 = (c0 < C) ? row[C + c0] : 0.f;
    float e1 = (c1 < C) ? row[C + c1] : 0.f;
    Wpc[c2 * O + o] = pack2(e0, e1);
}

// ---------------- weight transpose for W5: Wt[c][o] = W[o][c] ----------------
__global__ void transpose_kernel(const float* __restrict__ W, float* __restrict__ Wt,
                                 int O, int Cin) {
    int i = blockIdx.x * 256 + threadIdx.x;
    if (i < O * Cin) {
        int o = i / Cin;
        int c = i - o * Cin;
        Wt[c * O + o] = W[i];
    }
}

// ---------------- squared norms: one warp per point ----------------
__global__ void norms_kernel(const float* __restrict__ X, int C) {
    int p = blockIdx.x * 4 + (threadIdx.x >> 5);
    int lane = threadIdx.x & 31;
    const float* row = X + (size_t)p * C;
    float s = 0.f;
    for (int c = lane; c < C; c += 32) { float v = row[c]; s += v * v; }
    #pragma unroll
    for (int off = 16; off; off >>= 1) s += __shfl_down_sync(0xffffffffu, s, off);
    if (lane == 0) d_xx[p] = s;
}

// ---------------- FUSED knn: 64-row block streams 32 m-tiles, keeps running top-20 ----------------
// Tile compute identical to old dist_kernel (same arithmetic -> same values).
// Top-20 maintenance: strict > admits; eviction = min-value slot with LARGEST index.
// This reproduces jax.lax.top_k set semantics (value desc, index asc tie-break).
template <int C>
__global__ void knn_kernel(const float* __restrict__ X) {
    int b = blockIdx.y;
    int n0 = blockIdx.x * 64;
    __shared__ __align__(16) float An[16][68];
    __shared__ __align__(16) float Am[16][68];
    __shared__ __align__(16) float T[64][64];
    __shared__ float tv[64][20];
    __shared__ int   ti[64][20];

    int tid = threadIdx.x;
    int jj = tid & 15, rr = tid >> 4;     // loader mapping
    int ty = tid >> 4, tx = tid & 15;     // compute mapping (4x4 microtile)
    int w = tid >> 5, lane = tid & 31;    // topk mapping: warp w owns rows w*8..w*8+7

    for (int e = tid; e < 64 * KNN; e += 256) {
        (&tv[0][0])[e] = NEGINF;
        (&ti[0][0])[e] = 0x7fffffff;
    }
    float rm[8];
    int   rs[8];
    #pragma unroll
    for (int r = 0; r < 8; r++) { rm[r] = NEGINF; rs[r] = 0; }

    const float* Xb = X + (size_t)b * NPTS * C;
    float xn_[4];
    #pragma unroll
    for (int i = 0; i < 4; i++) xn_[i] = d_xx[b * NPTS + n0 + ty * 4 + i];
    __syncthreads();

    for (int mt = 0; mt < NPTS / 64; mt++) {
        int m0 = mt * 64;
        u64 acc2[4][2];
        #pragma unroll
        for (int i = 0; i < 4; i++) { acc2[i][0] = 0ull; acc2[i][1] = 0ull; }

        for (int c0 = 0; c0 < C; c0 += 16) {
            int c = c0 + jj;
            bool cv = (c < C);
            #pragma unroll
            for (int q = 0; q < 4; q++) {
                int r = rr * 4 + q;
                An[jj][r] = cv ? Xb[(size_t)(n0 + r) * C + c] : 0.f;
                Am[jj][r] = cv ? Xb[(size_t)(m0 + r) * C + c] : 0.f;
            }
            __syncthreads();
            #pragma unroll
            for (int cc = 0; cc < 16; cc++) {
                float4 a4 = *(const float4*)&An[cc][ty * 4];
                ulonglong2 b2 = *(const ulonglong2*)&Am[cc][tx * 4];
                u64 ad;
                ad = pack2(a4.x, a4.x);
                acc2[0][0] = fma2(ad, b2.x, acc2[0][0]);
                acc2[0][1] = fma2(ad, b2.y, acc2[0][1]);
                ad = pack2(a4.y, a4.y);
                acc2[1][0] = fma2(ad, b2.x, acc2[1][0]);
                acc2[1][1] = fma2(ad, b2.y, acc2[1][1]);
                ad = pack2(a4.z, a4.z);
                acc2[2][0] = fma2(ad, b2.x, acc2[2][0]);
                acc2[2][1] = fma2(ad, b2.y, acc2[2][1]);
                ad = pack2(a4.w, a4.w);
                acc2[3][0] = fma2(ad, b2.x, acc2[3][0]);
                acc2[3][1] = fma2(ad, b2.y, acc2[3][1]);
            }
            __syncthreads();
        }

        float xm[4];
        #pragma unroll
        for (int j = 0; j < 4; j++) xm[j] = d_xx[b * NPTS + m0 + tx * 4 + j];
        #pragma unroll
        for (int i = 0; i < 4; i++) {
            float xn = xn_[i];
            float2 p01 = unpack2(acc2[i][0]);
            float2 p23 = unpack2(acc2[i][1]);
            float4 outv;
            outv.x = 2.f * p01.x - xn - xm[0];
            outv.y = 2.f * p01.y - xn - xm[1];
            outv.z = 2.f * p23.x - xn - xm[2];
            outv.w = 2.f * p23.y - xn - xm[3];
            *(float4*)&T[ty * 4 + i][tx * 4] = outv;
        }
        __syncthreads();

        // --- top-20 update: warp w owns rows w*8..w*8+7 ---
        #pragma unroll
        for (int r = 0; r < 8; r++) {
            int row = w * 8 + r;
            #pragma unroll
            for (int pass = 0; pass < 2; pass++) {
                float v = T[row][lane + 32 * pass];
                unsigned mask = __ballot_sync(0xffffffffu, v > rm[r]);
                while (mask) {
                    int src = __ffs(mask) - 1;
                    mask &= mask - 1;
                    float cv = __shfl_sync(0xffffffffu, v, src);
                    if (cv > rm[r]) {               // recheck: rm rose
                        int ci = m0 + src + 32 * pass;
                        if (lane == 0) { tv[row][rs[r]] = cv; ti[row][rs[r]] = ci; }
                        __syncwarp();
                        // recompute min (value asc, index desc tie-break -> evict largest-index min)
                        float mv = (lane < KNN) ? tv[row][lane] : POSINF;
                        int   mi = (lane < KNN) ? ti[row][lane] : -1;
                        int   sl = lane;
                        #pragma unroll
                        for (int off = 16; off; off >>= 1) {
                            float omv = __shfl_down_sync(0xffffffffu, mv, off);
                            int   omi = __shfl_down_sync(0xffffffffu, mi, off);
                            int   osl = __shfl_down_sync(0xffffffffu, sl, off);
                            if (omv < mv || (omv == mv && omi > mi)) { mv = omv; mi = omi; sl = osl; }
                        }
                        rm[r] = __shfl_sync(0xffffffffu, mv, 0);
                        rs[r] = __shfl_sync(0xffffffffu, sl, 0);
                    }
                }
            }
        }
        __syncthreads();
    }

    // write neighbor indices (order irrelevant downstream: max over k)
    #pragma unroll
    for (int r = 0; r < 8; r++) {
        int row = w * 8 + r;
        if (lane < KNN)
            d_idx[(size_t)(b * NPTS + n0 + row) * KNN + lane] = ti[row][lane];
    }
}

// ---------------- edge conv: 2 POINTS per block packed into f32x2 lanes ----------------
// thread o computes output channel o for both points; weights splat into both lanes.
template <int C, int Cp, int O>
__global__ void edge_kernel(const float* __restrict__ X,
                            const u64* __restrict__ Wpd, const u64* __restrict__ Wpc,
                            const float* __restrict__ g, const float* __restrict__ bias,
                            float* __restrict__ Y) {
    int p0 = blockIdx.x * 2;            // global point ids p0, p0+1 (same batch: 2048 even)
    int o = threadIdx.x;
    int b = p0 >> 11;
    __shared__ __align__(16) u64 xc2[Cp];
    __shared__ __align__(16) u64 diff2[KNN * Cp];
    __shared__ int nbr0[KNN], nbr1[KNN];

    if (o < KNN) nbr0[o] = d_idx[(size_t)p0 * KNN + o];
    else if (o < 2 * KNN) nbr1[o - KNN] = d_idx[(size_t)(p0 + 1) * KNN + (o - KNN)];
    for (int c = o; c < Cp; c += O) {
        float a = (c < C) ? X[(size_t)p0 * C + c] : 0.f;
        float d = (c < C) ? X[(size_t)(p0 + 1) * C + c] : 0.f;
        xc2[c] = pack2(a, d);
    }
    __syncthreads();
    const float* Xb = X + (size_t)b * NPTS * C;
    for (int e = o; e < KNN * Cp; e += O) {
        int k = e / Cp, c = e - k * Cp;
        float v0 = 0.f, v1 = 0.f;
        if (c < C) {
            float2 xc = unpack2(xc2[c]);
            v0 = Xb[(size_t)nbr0[k] * C + c] - xc.x;
            v1 = Xb[(size_t)nbr1[k] * C + c] - xc.y;
        }
        diff2[e] = pack2(v0, v1);
    }
    __syncthreads();

    // center term for both points
    u64 cen2 = 0ull;
    #pragma unroll 4
    for (int c2 = 0; c2 < Cp / 2; c2++) {
        float2 wp = unpack2(Wpc[c2 * O + o]);
        cen2 = fma2(xc2[2 * c2],     pack2(wp.x, wp.x), cen2);
        cen2 = fma2(xc2[2 * c2 + 1], pack2(wp.y, wp.y), cen2);
    }

    u64 acc2[KNN];
    #pragma unroll
    for (int k = 0; k < KNN; k++) acc2[k] = 0ull;

    for (int c2 = 0; c2 < Cp / 2; c2++) {
        float2 wp = unpack2(Wpd[c2 * O + o]);
        u64 w0 = pack2(wp.x, wp.x);
        u64 w1 = pack2(wp.y, wp.y);
        #pragma unroll
        for (int k = 0; k < KNN; k++) {
            ulonglong2 dv = *(const ulonglong2*)&diff2[k * Cp + 2 * c2];
            acc2[k] = fma2(dv.x, w0, acc2[k]);
            acc2[k] = fma2(dv.y, w1, acc2[k]);
        }
    }

    float scale = g[o] * rsqrtf(1.f + 1e-5f);
    float bb = bias[o];
    float2 cen = unpack2(cen2);
    float m0 = NEGINF, m1 = NEGINF;
    #pragma unroll
    for (int k = 0; k < KNN; k++) {
        float2 t = unpack2(acc2[k]);
        float h0 = (t.x + cen.x) * scale + bb;
        float h1 = (t.y + cen.y) * scale + bb;
        h0 = (h0 >= 0.f) ? h0 : 0.2f * h0;
        h1 = (h1 >= 0.f) ? h1 : 0.2f * h1;
        m0 = fmaxf(m0, h0);
        m1 = fmaxf(m1, h1);
    }
    Y[(size_t)p0 * O + o] = m0;
    Y[(size_t)(p0 + 1) * O + o] = m1;
}

// ---------------- init h5 to -inf ----------------
__global__ void init_h5() {
    d_h5[blockIdx.x * blockDim.x + threadIdx.x] = NEGINF;
}

// ---------------- concat + W5 + bn/lrelu + max over N (per batch), f32x2 ----------------
__global__ void fuse_kernel(const float* __restrict__ g5, const float* __restrict__ b5) {
    int b = blockIdx.y;
    int n0 = blockIdx.x * 16;
    int t = threadIdx.x;                 // 256 threads
    __shared__ __align__(16) float xc[512][18];   // [channel][point], padded stride
    for (int e = t; e < 16 * 512; e += 256) {
        int pp = e >> 9, c = e & 511;
        int p = b * NPTS + n0 + pp;
        float v;
        if      (c < 64)  v = d_x1[(size_t)p * 64  + c];
        else if (c < 128) v = d_x2[(size_t)p * 64  + (c - 64)];
        else if (c < 256) v = d_x3[(size_t)p * 128 + (c - 128)];
        else              v = d_x4[(size_t)p * 256 + (c - 256)];
        xc[c][pp] = v;
    }
    __syncthreads();

    u64 a0[8], a1[8];
    #pragma unroll
    for (int q = 0; q < 8; q++) { a0[q] = 0ull; a1[q] = 0ull; }
    int o0 = t, o1 = t + 256;
    #pragma unroll 2
    for (int c = 0; c < 512; c++) {
        float w0 = d_W5t[c * 512 + o0];
        float w1 = d_W5t[c * 512 + o1];
        u64 w02 = pack2(w0, w0);
        u64 w12 = pack2(w1, w1);
        #pragma unroll
        for (int q = 0; q < 8; q++) {
            u64 xv = *(const u64*)&xc[c][2 * q];
            a0[q] = fma2(xv, w02, a0[q]);
            a1[q] = fma2(xv, w12, a1[q]);
        }
    }
    float s0 = g5[o0] * rsqrtf(1.f + 1e-5f), s1 = g5[o1] * rsqrtf(1.f + 1e-5f);
    float c0 = b5[o0], c1 = b5[o1];
    float m0 = NEGINF, m1 = NEGINF;
    #pragma unroll
    for (int q = 0; q < 8; q++) {
        float2 v0 = unpack2(a0[q]);
        float2 v1 = unpack2(a1[q]);
        float h;
        h = v0.x * s0 + c0; h = (h >= 0.f) ? h : 0.2f * h; m0 = fmaxf(m0, h);
        h = v0.y * s0 + c0; h = (h >= 0.f) ? h : 0.2f * h; m0 = fmaxf(m0, h);
        h = v1.x * s1 + c1; h = (h >= 0.f) ? h : 0.2f * h; m1 = fmaxf(m1, h);
        h = v1.y * s1 + c1; h = (h >= 0.f) ? h : 0.2f * h; m1 = fmaxf(m1, h);
    }
    atomicMaxFloat(&d_h5[b * 512 + o0], m0);
    atomicMaxFloat(&d_h5[b * 512 + o1], m1);
}

// ---------------- final: feat copy + embedding GEMV ----------------
__global__ void final_kernel(const float* __restrict__ Wemb, float* __restrict__ out) {
    int b = blockIdx.x;
    int t = threadIdx.x;                 // 512 threads
    __shared__ float h[512];
    float v = d_h5[b * 512 + t];
    h[t] = v;
    out[b * 512 + t] = v;                // feat (8,1,512)
    __syncthreads();
    if (t < 256) {
        float s = 0.f;
        #pragma unroll 4
        for (int c = 0; c < 512; c++) s += h[c] * Wemb[t * 512 + c];
        out[BATCH * 512 + b * 256 + t] = s;   // embedding (8,256)
    }
}

// ---------------- launch ----------------
extern "C" void kernel_launch(void* const* d_in, const int* in_sizes, int n_in,
                              void* d_out, int out_size) {
    const float* x    = (const float*)d_in[0];
    const float* W1   = (const float*)d_in[1];
    const float* g1   = (const float*)d_in[2];
    const float* b1   = (const float*)d_in[3];
    const float* W2   = (const float*)d_in[4];
    const float* g2   = (const float*)d_in[5];
    const float* b2   = (const float*)d_in[6];
    const float* W3   = (const float*)d_in[7];
    const float* g3   = (const float*)d_in[8];
    const float* b3   = (const float*)d_in[9];
    const float* W4   = (const float*)d_in[10];
    const float* g4   = (const float*)d_in[11];
    const float* b4   = (const float*)d_in[12];
    const float* W5   = (const float*)d_in[13];
    const float* g5   = (const float*)d_in[14];
    const float* b5   = (const float*)d_in[15];
    const float* Wemb = (const float*)d_in[16];
    float* out = (float*)d_out;

    float *pW5t, *px1, *px2, *px3, *px4;
    u64 *pWp1d, *pWp1c, *pWp2d, *pWp2c, *pWp3d, *pWp3c, *pWp4d, *pWp4c;
    cudaGetSymbolAddress((void**)&pW5t, d_W5t);
    cudaGetSymbolAddress((void**)&px1, d_x1);
    cudaGetSymbolAddress((void**)&px2, d_x2);
    cudaGetSymbolAddress((void**)&px3, d_x3);
    cudaGetSymbolAddress((void**)&px4, d_x4);
    cudaGetSymbolAddress((void**)&pWp1d, d_Wp1d);
    cudaGetSymbolAddress((void**)&pWp1c, d_Wp1c);
    cudaGetSymbolAddress((void**)&pWp2d, d_Wp2d);
    cudaGetSymbolAddress((void**)&pWp2c, d_Wp2c);
    cudaGetSymbolAddress((void**)&pWp3d, d_Wp3d);
    cudaGetSymbolAddress((void**)&pWp3c, d_Wp3c);
    cudaGetSymbolAddress((void**)&pWp4d, d_Wp4d);
    cudaGetSymbolAddress((void**)&pWp4c, d_Wp4c);

    pack_kernel<<<1, 256>>>(W1, pWp1d, pWp1c, 64, 3, 4);
    pack_kernel<<<(32 * 64 + 255) / 256, 256>>>(W2, pWp2d, pWp2c, 64, 64, 64);
    pack_kernel<<<(32 * 128 + 255) / 256, 256>>>(W3, pWp3d, pWp3c, 128, 64, 64);
    pack_kernel<<<(64 * 256 + 255) / 256, 256>>>(W4, pWp4d, pWp4c, 256, 128, 128);
    transpose_kernel<<<(512 * 512 + 255) / 256, 256>>>(W5, pW5t, 512, 512);

    dim3 kg(NPTS / 64, BATCH);           // 32 x 8 = 256 blocks
    int nrows = BATCH * NPTS;            // 16384
    int nblk2 = nrows / 2;               // 8192 (2 points per edge block)

    // Layer 1: C=3 -> O=64
    norms_kernel<<<nrows / 4, 128>>>(x, 3);
    knn_kernel<3><<<kg, 256>>>(x);
    edge_kernel<3, 4, 64><<<nblk2, 64>>>(x, pWp1d, pWp1c, g1, b1, px1);

    // Layer 2: C=64 -> O=64
    norms_kernel<<<nrows / 4, 128>>>(px1, 64);
    knn_kernel<64><<<kg, 256>>>(px1);
    edge_kernel<64, 64, 64><<<nblk2, 64>>>(px1, pWp2d, pWp2c, g2, b2, px2);

    // Layer 3: C=64 -> O=128
    norms_kernel<<<nrows / 4, 128>>>(px2, 64);
    knn_kernel<64><<<kg, 256>>>(px2);
    edge_kernel<64, 64, 128><<<nblk2, 128>>>(px2, pWp3d, pWp3c, g3, b3, px3);

    // Layer 4: C=128 -> O=256
    norms_kernel<<<nrows / 4, 128>>>(px3, 128);
    knn_kernel<128><<<kg, 256>>>(px3);
    edge_kernel<128, 128, 256><<<nblk2, 256>>>(px3, pWp4d, pWp4c, g4, b4, px4);

    // Final fuse + reductions
    init_h5<<<8, 512>>>();
    fuse_kernel<<<dim3(NPTS / 16, BATCH), 256>>>(g5, b5);
    final_kernel<<<BATCH, 512>>>(Wemb, out);
}

// round 9
// speedup vs baseline: 1.2780x; 1.2780x over previous
#include <cuda_runtime.h>
#include <cstdint>

#define NPTS 2048
#define BATCH 8
#define KNN 20
#define NEGINF __int_as_float(0xff800000)

typedef unsigned long long u64;

// ---------------- static device scratch (no allocation allowed) ----------------
__device__ float d_S[(size_t)BATCH * NPTS * NPTS];   // 134 MB score matrix
__device__ int   d_idx[BATCH * NPTS * KNN];
__device__ float d_xx[BATCH * NPTS];
__device__ float d_x1[BATCH * NPTS * 64];
__device__ float d_x2[BATCH * NPTS * 64];
__device__ float d_x3[BATCH * NPTS * 128];
__device__ float d_x4[BATCH * NPTS * 256];
// packed edge-conv weights: diff part and center part, u64 = {W[o][2c], W[o][2c+1]}
__device__ u64  d_Wp1d[2 * 64],    d_Wp1c[2 * 64];      // C=3 -> Cp=4
__device__ u64  d_Wp2d[32 * 64],   d_Wp2c[32 * 64];     // C=64
__device__ u64  d_Wp3d[32 * 128],  d_Wp3c[32 * 128];    // C=64
__device__ u64  d_Wp4d[64 * 256],  d_Wp4c[64 * 256];    // C=128
__device__ float d_W5t[512 * 512];
__device__ float d_h5[BATCH * 512];

// ---------------- f32x2 helpers ----------------
__device__ __forceinline__ u64 fma2(u64 a, u64 b, u64 c) {
    u64 d;
    asm("fma.rn.f32x2 %0, %1, %2, %3;" : "=l"(d) : "l"(a), "l"(b), "l"(c));
    return d;
}
__device__ __forceinline__ u64 pack2(float lo, float hi) {
    u64 d;
    asm("mov.b64 %0, {%1, %2};" : "=l"(d) : "f"(lo), "f"(hi));
    return d;
}
__device__ __forceinline__ float2 unpack2(u64 v) {
    float2 r;
    asm("mov.b64 {%0, %1}, %2;" : "=f"(r.x), "=f"(r.y) : "l"(v));
    return r;
}

__device__ __forceinline__ void atomicMaxFloat(float* addr, float v) {
    if (v >= 0.f) atomicMax((int*)addr, __float_as_int(v));
    else          atomicMin((unsigned int*)addr, __float_as_uint(v));
}

// ---------------- one prep kernel: all weight packing + W5 transpose + h5 init ----------------
__device__ __forceinline__ void pack_one(const float* __restrict__ W, u64* __restrict__ Wpd,
                                         u64* __restrict__ Wpc, int O, int C, int i) {
    int c2 = i / O, o = i - c2 * O;
    int c0 = 2 * c2, c1 = 2 * c2 + 1;
    const float* row = W + (size_t)o * 2 * C;
    float a0 = (c0 < C) ? row[c0] : 0.f;
    float a1 = (c1 < C) ? row[c1] : 0.f;
    Wpd[c2 * O + o] = pack2(a0, a1);
    float e0 = (c0 < C) ? row[C + c0] : 0.f;
    float e1 = (c1 < C) ? row[C + c1] : 0.f;
    Wpc[c2 * O + o] = pack2(e0, e1);
}

__global__ void prep_kernel(const float* __restrict__ W1, const float* __restrict__ W2,
                            const float* __restrict__ W3, const float* __restrict__ W4,
                            const float* __restrict__ W5) {
    int tid = blockIdx.x * blockDim.x + threadIdx.x;
    int stride = gridDim.x * blockDim.x;
    for (int i = tid; i < 2 * 64; i += stride)    pack_one(W1, d_Wp1d, d_Wp1c, 64, 3, i);
    for (int i = tid; i < 32 * 64; i += stride)   pack_one(W2, d_Wp2d, d_Wp2c, 64, 64, i);
    for (int i = tid; i < 32 * 128; i += stride)  pack_one(W3, d_Wp3d, d_Wp3c, 128, 64, i);
    for (int i = tid; i < 64 * 256; i += stride)  pack_one(W4, d_Wp4d, d_Wp4c, 256, 128, i);
    for (int i = tid; i < 512 * 512; i += stride) {
        int o = i >> 9, c = i & 511;
        d_W5t[c * 512 + o] = W5[i];
    }
    for (int i = tid; i < BATCH * 512; i += stride) d_h5[i] = NEGINF;
}

// ---------------- squared norms of the raw input (layer 1 only) ----------------
__global__ void norms_kernel(const float* __restrict__ X, int C) {
    int p = blockIdx.x * 4 + (threadIdx.x >> 5);
    int lane = threadIdx.x & 31;
    const float* row = X + (size_t)p * C;
    float s = 0.f;
    for (int c = lane; c < C; c += 32) { float v = row[c]; s += v * v; }
    #pragma unroll
    for (int off = 16; off; off >>= 1) s += __shfl_down_sync(0xffffffffu, s, off);
    if (lane == 0) d_xx[p] = s;
}

// ---------------- neg squared distance: 64x64 tiles, 4x4 microtiles, f32x2 ----------------
template <int C>
__global__ void dist_kernel(const float* __restrict__ X) {
    int b = blockIdx.z;
    int n0 = blockIdx.y * 64, m0 = blockIdx.x * 64;
    __shared__ __align__(16) float An[16][68];
    __shared__ __align__(16) float Am[16][68];
    int tid = threadIdx.x;
    int jj = tid & 15, rr = tid >> 4;     // loader: channel jj, rows rr*4..rr*4+3
    int ty = tid >> 4, tx = tid & 15;     // compute: 4x4 tile at (ty*4, tx*4)
    u64 acc2[4][2];
    #pragma unroll
    for (int i = 0; i < 4; i++) { acc2[i][0] = 0ull; acc2[i][1] = 0ull; }
    const float* Xb = X + (size_t)b * NPTS * C;

    for (int c0 = 0; c0 < C; c0 += 16) {
        int c = c0 + jj;
        bool cv = (c < C);
        #pragma unroll
        for (int q = 0; q < 4; q++) {
            int r = rr * 4 + q;
            An[jj][r] = cv ? Xb[(size_t)(n0 + r) * C + c] : 0.f;
            Am[jj][r] = cv ? Xb[(size_t)(m0 + r) * C + c] : 0.f;
        }
        __syncthreads();
        #pragma unroll
        for (int cc = 0; cc < 16; cc++) {
            float4 a4 = *(const float4*)&An[cc][ty * 4];
            ulonglong2 b2 = *(const ulonglong2*)&Am[cc][tx * 4];
            u64 ad;
            ad = pack2(a4.x, a4.x);
            acc2[0][0] = fma2(ad, b2.x, acc2[0][0]);
            acc2[0][1] = fma2(ad, b2.y, acc2[0][1]);
            ad = pack2(a4.y, a4.y);
            acc2[1][0] = fma2(ad, b2.x, acc2[1][0]);
            acc2[1][1] = fma2(ad, b2.y, acc2[1][1]);
            ad = pack2(a4.z, a4.z);
            acc2[2][0] = fma2(ad, b2.x, acc2[2][0]);
            acc2[2][1] = fma2(ad, b2.y, acc2[2][1]);
            ad = pack2(a4.w, a4.w);
            acc2[3][0] = fma2(ad, b2.x, acc2[3][0]);
            acc2[3][1] = fma2(ad, b2.y, acc2[3][1]);
        }
        __syncthreads();
    }

    float xm[4];
    #pragma unroll
    for (int j = 0; j < 4; j++) xm[j] = d_xx[b * NPTS + m0 + tx * 4 + j];
    #pragma unroll
    for (int i = 0; i < 4; i++) {
        int n = n0 + ty * 4 + i;
        float xn = d_xx[b * NPTS + n];
        float2 p01 = unpack2(acc2[i][0]);
        float2 p23 = unpack2(acc2[i][1]);
        float4 outv;
        outv.x = 2.f * p01.x - xn - xm[0];
        outv.y = 2.f * p01.y - xn - xm[1];
        outv.z = 2.f * p23.x - xn - xm[2];
        outv.w = 2.f * p23.y - xn - xm[3];
        *(float4*)&d_S[((size_t)b * NPTS + n) * NPTS + m0 + tx * 4] = outv;
    }
}

// ---------------- top-K per row: one warp per row, 20 argmax sweeps ----------------
__global__ void topk_kernel() {
    __shared__ float buf[4][NPTS];
    int w = threadIdx.x >> 5, lane = threadIdx.x & 31;
    int row = blockIdx.x * 4 + w;                // global row = b*NPTS + n
    const float* S = d_S + (size_t)row * NPTS;
    for (int m = lane; m < NPTS; m += 32) buf[w][m] = S[m];
    __syncwarp();
    for (int it = 0; it < KNN; it++) {
        float v = NEGINF; int mi = NPTS;
        for (int m = lane; m < NPTS; m += 32) {
            float x = buf[w][m];
            if (x > v) { v = x; mi = m; }       // first (smallest m) max kept
        }
        #pragma unroll
        for (int off = 16; off; off >>= 1) {
            float ov = __shfl_down_sync(0xffffffffu, v, off);
            int   oi = __shfl_down_sync(0xffffffffu, mi, off);
            if (ov > v || (ov == v && oi < mi)) { v = ov; mi = oi; }
        }
        mi = __shfl_sync(0xffffffffu, mi, 0);
        if (lane == 0) { d_idx[row * KNN + it] = mi; buf[w][mi] = NEGINF; }
        __syncwarp();
    }
}

// ---------------- edge conv: 2 POINTS per block packed into f32x2 lanes ----------------
// thread o computes output channel o for both points; weights splat into both lanes.
// WN: also write sum(Y[p][:]^2) to d_xx (feeds the next layer's dist) while Y is in regs.
template <int C, int Cp, int O, bool WN>
__global__ void edge_kernel(const float* __restrict__ X,
                            const u64* __restrict__ Wpd, const u64* __restrict__ Wpc,
                            const float* __restrict__ g, const float* __restrict__ bias,
                            float* __restrict__ Y) {
    int p0 = blockIdx.x * 2;            // global point ids p0, p0+1 (same batch: 2048 even)
    int o = threadIdx.x;
    int b = p0 >> 11;
    __shared__ __align__(16) u64 xc2[Cp];
    __shared__ __align__(16) u64 diff2[KNN * Cp];
    __shared__ int nbr0[KNN], nbr1[KNN];

    if (o < KNN) nbr0[o] = d_idx[(size_t)p0 * KNN + o];
    else if (o < 2 * KNN) nbr1[o - KNN] = d_idx[(size_t)(p0 + 1) * KNN + (o - KNN)];
    for (int c = o; c < Cp; c += O) {
        float a = (c < C) ? X[(size_t)p0 * C + c] : 0.f;
        float d = (c < C) ? X[(size_t)(p0 + 1) * C + c] : 0.f;
        xc2[c] = pack2(a, d);
    }
    __syncthreads();
    const float* Xb = X + (size_t)b * NPTS * C;
    for (int e = o; e < KNN * Cp; e += O) {
        int k = e / Cp, c = e - k * Cp;
        float v0 = 0.f, v1 = 0.f;
        if (c < C) {
            float2 xc = unpack2(xc2[c]);
            v0 = Xb[(size_t)nbr0[k] * C + c] - xc.x;
            v1 = Xb[(size_t)nbr1[k] * C + c] - xc.y;
        }
        diff2[e] = pack2(v0, v1);
    }
    __syncthreads();

    // center term for both points
    u64 cen2 = 0ull;
    #pragma unroll 4
    for (int c2 = 0; c2 < Cp / 2; c2++) {
        float2 wp = unpack2(Wpc[c2 * O + o]);
        cen2 = fma2(xc2[2 * c2],     pack2(wp.x, wp.x), cen2);
        cen2 = fma2(xc2[2 * c2 + 1], pack2(wp.y, wp.y), cen2);
    }

    u64 acc2[KNN];
    #pragma unroll
    for (int k = 0; k < KNN; k++) acc2[k] = 0ull;

    for (int c2 = 0; c2 < Cp / 2; c2++) {
        float2 wp = unpack2(Wpd[c2 * O + o]);
        u64 w0 = pack2(wp.x, wp.x);
        u64 w1 = pack2(wp.y, wp.y);
        #pragma unroll
        for (int k = 0; k < KNN; k++) {
            ulonglong2 dv = *(const ulonglong2*)&diff2[k * Cp + 2 * c2];
            acc2[k] = fma2(dv.x, w0, acc2[k]);
            acc2[k] = fma2(dv.y, w1, acc2[k]);
        }
    }

    float scale = g[o] * rsqrtf(1.f + 1e-5f);
    float bb = bias[o];
    float2 cen = unpack2(cen2);
    float m0 = NEGINF, m1 = NEGINF;
    #pragma unroll
    for (int k = 0; k < KNN; k++) {
        float2 t = unpack2(acc2[k]);
        float h0 = (t.x + cen.x) * scale + bb;
        float h1 = (t.y + cen.y) * scale + bb;
        h0 = (h0 >= 0.f) ? h0 : 0.2f * h0;
        h1 = (h1 >= 0.f) ? h1 : 0.2f * h1;
        m0 = fmaxf(m0, h0);
        m1 = fmaxf(m1, h1);
    }
    Y[(size_t)p0 * O + o] = m0;
    Y[(size_t)(p0 + 1) * O + o] = m1;

    if (WN) {   // block-reduce sum of squares -> next layer's xx
        __shared__ float r0[O / 32], r1[O / 32];
        int w = o >> 5, lane = o & 31;
        float s0 = m0 * m0, s1 = m1 * m1;
        #pragma unroll
        for (int off = 16; off; off >>= 1) {
            s0 += __shfl_down_sync(0xffffffffu, s0, off);
            s1 += __shfl_down_sync(0xffffffffu, s1, off);
        }
        if (lane == 0) { r0[w] = s0; r1[w] = s1; }
        __syncthreads();
        if (o == 0) {
            float t0 = 0.f, t1 = 0.f;
            #pragma unroll
            for (int i = 0; i < O / 32; i++) { t0 += r0[i]; t1 += r1[i]; }
            d_xx[p0] = t0;
            d_xx[p0 + 1] = t1;
        }
    }
}

// ---------------- concat + W5 + bn/lrelu + max over N (per batch), f32x2 ----------------
__global__ void fuse_kernel(const float* __restrict__ g5, const float* __restrict__ b5) {
    int b = blockIdx.y;
    int n0 = blockIdx.x * 16;
    int t = threadIdx.x;                 // 256 threads
    __shared__ __align__(16) float xc[512][18];   // [channel][point], padded stride
    for (int e = t; e < 16 * 512; e += 256) {
        int pp = e >> 9, c = e & 511;
        int p = b * NPTS + n0 + pp;
        float v;
        if      (c < 64)  v = d_x1[(size_t)p * 64  + c];
        else if (c < 128) v = d_x2[(size_t)p * 64  + (c - 64)];
        else if (c < 256) v = d_x3[(size_t)p * 128 + (c - 128)];
        else              v = d_x4[(size_t)p * 256 + (c - 256)];
        xc[c][pp] = v;
    }
    __syncthreads();

    u64 a0[8], a1[8];
    #pragma unroll
    for (int q = 0; q < 8; q++) { a0[q] = 0ull; a1[q] = 0ull; }
    int o0 = t, o1 = t + 256;
    #pragma unroll 2
    for (int c = 0; c < 512; c++) {
        float w0 = d_W5t[c * 512 + o0];
        float w1 = d_W5t[c * 512 + o1];
        u64 w02 = pack2(w0, w0);
        u64 w12 = pack2(w1, w1);
        #pragma unroll
        for (int q = 0; q < 8; q++) {
            u64 xv = *(const u64*)&xc[c][2 * q];
            a0[q] = fma2(xv, w02, a0[q]);
            a1[q] = fma2(xv, w12, a1[q]);
        }
    }
    float s0 = g5[o0] * rsqrtf(1.f + 1e-5f), s1 = g5[o1] * rsqrtf(1.f + 1e-5f);
    float c0 = b5[o0], c1 = b5[o1];
    float m0 = NEGINF, m1 = NEGINF;
    #pragma unroll
    for (int q = 0; q < 8; q++) {
        float2 v0 = unpack2(a0[q]);
        float2 v1 = unpack2(a1[q]);
        float h;
        h = v0.x * s0 + c0; h = (h >= 0.f) ? h : 0.2f * h; m0 = fmaxf(m0, h);
        h = v0.y * s0 + c0; h = (h >= 0.f) ? h : 0.2f * h; m0 = fmaxf(m0, h);
        h = v1.x * s1 + c1; h = (h >= 0.f) ? h : 0.2f * h; m1 = fmaxf(m1, h);
        h = v1.y * s1 + c1; h = (h >= 0.f) ? h : 0.2f * h; m1 = fmaxf(m1, h);
    }
    atomicMaxFloat(&d_h5[b * 512 + o0], m0);
    atomicMaxFloat(&d_h5[b * 512 + o1], m1);
}

// ---------------- final: feat copy + embedding GEMV ----------------
__global__ void final_kernel(const float* __restrict__ Wemb, float* __restrict__ out) {
    int b = blockIdx.x;
    int t = threadIdx.x;                 // 512 threads
    __shared__ float h[512];
    float v = d_h5[b * 512 + t];
    h[t] = v;
    out[b * 512 + t] = v;                // feat (8,1,512)
    __syncthreads();
    if (t < 256) {
        float s = 0.f;
        #pragma unroll 4
        for (int c = 0; c < 512; c++) s += h[c] * Wemb[t * 512 + c];
        out[BATCH * 512 + b * 256 + t] = s;   // embedding (8,256)
    }
}

// ---------------- launch ----------------
extern "C" void kernel_launch(void* const* d_in, const int* in_sizes, int n_in,
                              void* d_out, int out_size) {
    const float* x    = (const float*)d_in[0];
    const float* W1   = (const float*)d_in[1];
    const float* g1   = (const float*)d_in[2];
    const float* b1   = (const float*)d_in[3];
    const float* W2   = (const float*)d_in[4];
    const float* g2   = (const float*)d_in[5];
    const float* b2   = (const float*)d_in[6];
    const float* W3   = (const float*)d_in[7];
    const float* g3   = (const float*)d_in[8];
    const float* b3   = (const float*)d_in[9];
    const float* W4   = (const float*)d_in[10];
    const float* g4   = (const float*)d_in[11];
    const float* b4   = (const float*)d_in[12];
    const float* W5   = (const float*)d_in[13];
    const float* g5   = (const float*)d_in[14];
    const float* b5   = (const float*)d_in[15];
    const float* Wemb = (const float*)d_in[16];
    float* out = (float*)d_out;

    float *px1, *px2, *px3, *px4;
    u64 *pWp1d, *pWp1c, *pWp2d, *pWp2c, *pWp3d, *pWp3c, *pWp4d, *pWp4c;
    cudaGetSymbolAddress((void**)&px1, d_x1);
    cudaGetSymbolAddress((void**)&px2, d_x2);
    cudaGetSymbolAddress((void**)&px3, d_x3);
    cudaGetSymbolAddress((void**)&px4, d_x4);
    cudaGetSymbolAddress((void**)&pWp1d, d_Wp1d);
    cudaGetSymbolAddress((void**)&pWp1c, d_Wp1c);
    cudaGetSymbolAddress((void**)&pWp2d, d_Wp2d);
    cudaGetSymbolAddress((void**)&pWp2c, d_Wp2c);
    cudaGetSymbolAddress((void**)&pWp3d, d_Wp3d);
    cudaGetSymbolAddress((void**)&pWp3c, d_Wp3c);
    cudaGetSymbolAddress((void**)&pWp4d, d_Wp4d);
    cudaGetSymbolAddress((void**)&pWp4c, d_Wp4c);

    // launch 0: all prep (packs + W5 transpose + h5 init)
    prep_kernel<<<512, 256>>>(W1, W2, W3, W4, W5);

    dim3 dg(NPTS / 64, NPTS / 64, BATCH);
    int nrows = BATCH * NPTS;            // 16384
    int nblk2 = nrows / 2;               // 8192 (2 points per edge block)

    // Layer 1: C=3 -> O=64                      (launches 1-4)
    norms_kernel<<<nrows / 4, 128>>>(x, 3);
    dist_kernel<3><<<dg, 256>>>(x);
    topk_kernel<<<nrows / 4, 128>>>();
    edge_kernel<3, 4, 64, true><<<nblk2, 64>>>(x, pWp1d, pWp1c, g1, b1, px1);

    // Layer 2: C=64 -> O=64                     (launches 5-7; ncu -s 5 captures dist2)
    dist_kernel<64><<<dg, 256>>>(px1);
    topk_kernel<<<nrows / 4, 128>>>();
    edge_kernel<64, 64, 64, true><<<nblk2, 64>>>(px1, pWp2d, pWp2c, g2, b2, px2);

    // Layer 3: C=64 -> O=128
    dist_kernel<64><<<dg, 256>>>(px2);
    topk_kernel<<<nrows / 4, 128>>>();
    edge_kernel<64, 64, 128, true><<<nblk2, 128>>>(px2, pWp3d, pWp3c, g3, b3, px3);

    // Layer 4: C=128 -> O=256
    dist_kernel<128><<<dg, 256>>>(px3);
    topk_kernel<<<nrows / 4, 128>>>();
    edge_kernel<128, 128, 256, false><<<nblk2, 256>>>(px3, pWp4d, pWp4c, g4, b4, px4);

    // Final fuse + reductions
    fuse_kernel<<<dim3(NPTS / 16, BATCH), 256>>>(g5, b5);
    final_kernel<<<BATCH, 512>>>(Wemb, out);
}

// round 11
// speedup vs baseline: 1.3971x; 1.0932x over previous
#include <cuda_runtime.h>
#include <cstdint>

#define NPTS 2048
#define BATCH 8
#define KNN 20
#define NEGINF __int_as_float(0xff800000)

typedef unsigned long long u64;

// ---------------- static device scratch (no allocation allowed) ----------------
__device__ float d_S[(size_t)BATCH * NPTS * NPTS];   // 134 MB score matrix
__device__ int   d_idx[BATCH * NPTS * KNN];
__device__ float d_xx[BATCH * NPTS];
__device__ float d_x1[BATCH * NPTS * 64];
__device__ float d_x2[BATCH * NPTS * 64];
__device__ float d_x3[BATCH * NPTS * 128];
__device__ float d_x4[BATCH * NPTS * 256];
// packed edge-conv weights: diff part and center part, u64 = {W[o][2c], W[o][2c+1]}
__device__ u64  d_Wp1d[2 * 64],    d_Wp1c[2 * 64];      // C=3 -> Cp=4
__device__ u64  d_Wp2d[32 * 64],   d_Wp2c[32 * 64];     // C=64
__device__ u64  d_Wp3d[32 * 128],  d_Wp3c[32 * 128];    // C=64
__device__ u64  d_Wp4d[64 * 256],  d_Wp4c[64 * 256];    // C=128
__device__ float d_W5t[512 * 512];
__device__ float d_h5[BATCH * 512];

// ---------------- f32x2 helpers ----------------
__device__ __forceinline__ u64 fma2(u64 a, u64 b, u64 c) {
    u64 d;
    asm("fma.rn.f32x2 %0, %1, %2, %3;" : "=l"(d) : "l"(a), "l"(b), "l"(c));
    return d;
}
__device__ __forceinline__ u64 pack2(float lo, float hi) {
    u64 d;
    asm("mov.b64 %0, {%1, %2};" : "=l"(d) : "f"(lo), "f"(hi));
    return d;
}
__device__ __forceinline__ float2 unpack2(u64 v) {
    float2 r;
    asm("mov.b64 {%0, %1}, %2;" : "=f"(r.x), "=f"(r.y) : "l"(v));
    return r;
}

__device__ __forceinline__ void atomicMaxFloat(float* addr, float v) {
    if (v >= 0.f) atomicMax((int*)addr, __float_as_int(v));
    else          atomicMin((unsigned int*)addr, __float_as_uint(v));
}

// ---------------- one prep kernel: all weight packing + W5 transpose + h5 init ----------------
__device__ __forceinline__ void pack_one(const float* __restrict__ W, u64* __restrict__ Wpd,
                                         u64* __restrict__ Wpc, int O, int C, int i) {
    int c2 = i / O, o = i - c2 * O;
    int c0 = 2 * c2, c1 = 2 * c2 + 1;
    const float* row = W + (size_t)o * 2 * C;
    float a0 = (c0 < C) ? row[c0] : 0.f;
    float a1 = (c1 < C) ? row[c1] : 0.f;
    Wpd[c2 * O + o] = pack2(a0, a1);
    float e0 = (c0 < C) ? row[C + c0] : 0.f;
    float e1 = (c1 < C) ? row[C + c1] : 0.f;
    Wpc[c2 * O + o] = pack2(e0, e1);
}

__global__ void prep_kernel(const float* __restrict__ W1, const float* __restrict__ W2,
                            const float* __restrict__ W3, const float* __restrict__ W4,
                            const float* __restrict__ W5) {
    int tid = blockIdx.x * blockDim.x + threadIdx.x;
    int stride = gridDim.x * blockDim.x;
    for (int i = tid; i < 2 * 64; i += stride)    pack_one(W1, d_Wp1d, d_Wp1c, 64, 3, i);
    for (int i = tid; i < 32 * 64; i += stride)   pack_one(W2, d_Wp2d, d_Wp2c, 64, 64, i);
    for (int i = tid; i < 32 * 128; i += stride)  pack_one(W3, d_Wp3d, d_Wp3c, 128, 64, i);
    for (int i = tid; i < 64 * 256; i += stride)  pack_one(W4, d_Wp4d, d_Wp4c, 256, 128, i);
    for (int i = tid; i < 512 * 512; i += stride) {
        int o = i >> 9, c = i & 511;
        d_W5t[c * 512 + o] = W5[i];
    }
    for (int i = tid; i < BATCH * 512; i += stride) d_h5[i] = NEGINF;
}

// ---------------- squared norms of the raw input (layer 1 only) ----------------
__global__ void norms_kernel(const float* __restrict__ X, int C) {
    int p = blockIdx.x * 4 + (threadIdx.x >> 5);
    int lane = threadIdx.x & 31;
    const float* row = X + (size_t)p * C;
    float s = 0.f;
    for (int c = lane; c < C; c += 32) { float v = row[c]; s += v * v; }
    #pragma unroll
    for (int off = 16; off; off >>= 1) s += __shfl_down_sync(0xffffffffu, s, off);
    if (lane == 0) d_xx[p] = s;
}

// ---------------- neg squared distance: 64x64 tiles, 4x4 microtiles, f32x2 ----------------
template <int C>
__global__ void dist_kernel(const float* __restrict__ X) {
    int b = blockIdx.z;
    int n0 = blockIdx.y * 64, m0 = blockIdx.x * 64;
    __shared__ __align__(16) float An[16][68];
    __shared__ __align__(16) float Am[16][68];
    int tid = threadIdx.x;
    int jj = tid & 15, rr = tid >> 4;     // loader: channel jj, rows rr*4..rr*4+3
    int ty = tid >> 4, tx = tid & 15;     // compute: 4x4 tile at (ty*4, tx*4)
    u64 acc2[4][2];
    #pragma unroll
    for (int i = 0; i < 4; i++) { acc2[i][0] = 0ull; acc2[i][1] = 0ull; }
    const float* Xb = X + (size_t)b * NPTS * C;

    for (int c0 = 0; c0 < C; c0 += 16) {
        int c = c0 + jj;
        bool cv = (c < C);
        #pragma unroll
        for (int q = 0; q < 4; q++) {
            int r = rr * 4 + q;
            An[jj][r] = cv ? Xb[(size_t)(n0 + r) * C + c] : 0.f;
            Am[jj][r] = cv ? Xb[(size_t)(m0 + r) * C + c] : 0.f;
        }
        __syncthreads();
        #pragma unroll
        for (int cc = 0; cc < 16; cc++) {
            float4 a4 = *(const float4*)&An[cc][ty * 4];
            ulonglong2 b2 = *(const ulonglong2*)&Am[cc][tx * 4];
            u64 ad;
            ad = pack2(a4.x, a4.x);
            acc2[0][0] = fma2(ad, b2.x, acc2[0][0]);
            acc2[0][1] = fma2(ad, b2.y, acc2[0][1]);
            ad = pack2(a4.y, a4.y);
            acc2[1][0] = fma2(ad, b2.x, acc2[1][0]);
            acc2[1][1] = fma2(ad, b2.y, acc2[1][1]);
            ad = pack2(a4.z, a4.z);
            acc2[2][0] = fma2(ad, b2.x, acc2[2][0]);
            acc2[2][1] = fma2(ad, b2.y, acc2[2][1]);
            ad = pack2(a4.w, a4.w);
            acc2[3][0] = fma2(ad, b2.x, acc2[3][0]);
            acc2[3][1] = fma2(ad, b2.y, acc2[3][1]);
        }
        __syncthreads();
    }

    float xm[4];
    #pragma unroll
    for (int j = 0; j < 4; j++) xm[j] = d_xx[b * NPTS + m0 + tx * 4 + j];
    #pragma unroll
    for (int i = 0; i < 4; i++) {
        int n = n0 + ty * 4 + i;
        float xn = d_xx[b * NPTS + n];
        float2 p01 = unpack2(acc2[i][0]);
        float2 p23 = unpack2(acc2[i][1]);
        float4 outv;
        outv.x = 2.f * p01.x - xn - xm[0];
        outv.y = 2.f * p01.y - xn - xm[1];
        outv.z = 2.f * p23.x - xn - xm[2];
        outv.w = 2.f * p23.y - xn - xm[3];
        *(float4*)&d_S[((size_t)b * NPTS + n) * NPTS + m0 + tx * 4] = outv;
    }
}

// ---------------- top-K per row: per-lane top-3 tournament ----------------
// Each lane owns the stripe m = lane + 32t (t in [0,64)). Build a register-resident
// sorted top-3 per lane in one pass; then 20 rounds of warp argmax over lane heads.
// Winner lane shifts; rescans its stripe only when all 3 candidates are consumed
// (expected ~1 rescan per row). Tie-breaks: value desc, index asc -> matches
// jax.lax.top_k set semantics (validated by the round-8 kernel's insertion rules).
__global__ void topk_kernel() {
    __shared__ float buf[4][NPTS];
    int w = threadIdx.x >> 5, lane = threadIdx.x & 31;
    int row = blockIdx.x * 4 + w;                // global row = b*NPTS + n
    const float* S = d_S + (size_t)row * NPTS;
    float* B = buf[w];

    float lv0 = NEGINF, lv1 = NEGINF, lv2 = NEGINF;
    int   li0 = 0x7fffffff, li1 = 0x7fffffff, li2 = 0x7fffffff;

    // build: single pass, stage stripe into (lane-private) smem, keep top-3
    for (int t = 0; t < NPTS / 32; t++) {
        int m = lane + 32 * t;
        float v = S[m];
        B[m] = v;
        if (v > lv2) {                          // strict >: equal keeps earlier (smaller m)
            if (v > lv1) {
                if (v > lv0) { lv2 = lv1; li2 = li1; lv1 = lv0; li1 = li0; lv0 = v; li0 = m; }
                else         { lv2 = lv1; li2 = li1; lv1 = v; li1 = m; }
            } else           { lv2 = v; li2 = m; }
        }
    }

    for (int r = 0; r < KNN; r++) {
        // warp argmax over lane heads: value desc, index asc
        float v = lv0; int mi = li0; int sl = lane;
        #pragma unroll
        for (int off = 16; off; off >>= 1) {
            float ov = __shfl_down_sync(0xffffffffu, v, off);
            int   oi = __shfl_down_sync(0xffffffffu, mi, off);
            int   osl = __shfl_down_sync(0xffffffffu, sl, off);
            if (ov > v || (ov == v && oi < mi)) { v = ov; mi = oi; sl = osl; }
        }
        int wi = __shfl_sync(0xffffffffu, mi, 0);
        int wl = __shfl_sync(0xffffffffu, sl, 0);
        if (lane == 0) d_idx[(size_t)row * KNN + r] = wi;
        if (lane == wl) {
            B[wi] = NEGINF;                     // mark emitted (own stripe)
            lv0 = lv1; li0 = li1;
            lv1 = lv2; li1 = li2;
            lv2 = NEGINF; li2 = 0x7fffffff;
            if (li0 == 0x7fffffff) {            // exhausted: rescan own stripe
                lv0 = lv1 = lv2 = NEGINF;
                li0 = li1 = li2 = 0x7fffffff;
                for (int t = 0; t < NPTS / 32; t++) {
                    int m = lane + 32 * t;
                    float vv = B[m];
                    if (vv > lv2) {
                        if (vv > lv1) {
                            if (vv > lv0) { lv2 = lv1; li2 = li1; lv1 = lv0; li1 = li0; lv0 = vv; li0 = m; }
                            else          { lv2 = lv1; li2 = li1; lv1 = vv; li1 = m; }
                        } else            { lv2 = vv; li2 = m; }
                    }
                }
            }
        }
    }
}

// ---------------- edge conv: 2 POINTS per block packed into f32x2 lanes ----------------
// thread o computes output channel o for both points; weights splat into both lanes.
// WN: also write sum(Y[p][:]^2) to d_xx (feeds the next layer's dist) while Y is in regs.
template <int C, int Cp, int O, bool WN>
__global__ void edge_kernel(const float* __restrict__ X,
                            const u64* __restrict__ Wpd, const u64* __restrict__ Wpc,
                            const float* __restrict__ g, const float* __restrict__ bias,
                            float* __restrict__ Y) {
    int p0 = blockIdx.x * 2;            // global point ids p0, p0+1 (same batch: 2048 even)
    int o = threadIdx.x;
    int b = p0 >> 11;
    __shared__ __align__(16) u64 xc2[Cp];
    __shared__ __align__(16) u64 diff2[KNN * Cp];
    __shared__ int nbr0[KNN], nbr1[KNN];

    if (o < KNN) nbr0[o] = d_idx[(size_t)p0 * KNN + o];
    else if (o < 2 * KNN) nbr1[o - KNN] = d_idx[(size_t)(p0 + 1) * KNN + (o - KNN)];
    for (int c = o; c < Cp; c += O) {
        float a = (c < C) ? X[(size_t)p0 * C + c] : 0.f;
        float d = (c < C) ? X[(size_t)(p0 + 1) * C + c] : 0.f;
        xc2[c] = pack2(a, d);
    }
    __syncthreads();
    const float* Xb = X + (size_t)b * NPTS * C;
    for (int e = o; e < KNN * Cp; e += O) {
        int k = e / Cp, c = e - k * Cp;
        float v0 = 0.f, v1 = 0.f;
        if (c < C) {
            float2 xc = unpack2(xc2[c]);
            v0 = Xb[(size_t)nbr0[k] * C + c] - xc.x;
            v1 = Xb[(size_t)nbr1[k] * C + c] - xc.y;
        }
        diff2[e] = pack2(v0, v1);
    }
    __syncthreads();

    // center term for both points
    u64 cen2 = 0ull;
    #pragma unroll 4
    for (int c2 = 0; c2 < Cp / 2; c2++) {
        float2 wp = unpack2(Wpc[c2 * O + o]);
        cen2 = fma2(xc2[2 * c2],     pack2(wp.x, wp.x), cen2);
        cen2 = fma2(xc2[2 * c2 + 1], pack2(wp.y, wp.y), cen2);
    }

    u64 acc2[KNN];
    #pragma unroll
    for (int k = 0; k < KNN; k++) acc2[k] = 0ull;

    for (int c2 = 0; c2 < Cp / 2; c2++) {
        float2 wp = unpack2(Wpd[c2 * O + o]);
        u64 w0 = pack2(wp.x, wp.x);
        u64 w1 = pack2(wp.y, wp.y);
        #pragma unroll
        for (int k = 0; k < KNN; k++) {
            ulonglong2 dv = *(const ulonglong2*)&diff2[k * Cp + 2 * c2];
            acc2[k] = fma2(dv.x, w0, acc2[k]);
            acc2[k] = fma2(dv.y, w1, acc2[k]);
        }
    }

    float scale = g[o] * rsqrtf(1.f + 1e-5f);
    float bb = bias[o];
    float2 cen = unpack2(cen2);
    float m0 = NEGINF, m1 = NEGINF;
    #pragma unroll
    for (int k = 0; k < KNN; k++) {
        float2 t = unpack2(acc2[k]);
        float h0 = (t.x + cen.x) * scale + bb;
        float h1 = (t.y + cen.y) * scale + bb;
        h0 = (h0 >= 0.f) ? h0 : 0.2f * h0;
        h1 = (h1 >= 0.f) ? h1 : 0.2f * h1;
        m0 = fmaxf(m0, h0);
        m1 = fmaxf(m1, h1);
    }
    Y[(size_t)p0 * O + o] = m0;
    Y[(size_t)(p0 + 1) * O + o] = m1;

    if (WN) {   // block-reduce sum of squares -> next layer's xx
        __shared__ float r0[O / 32], r1[O / 32];
        int w = o >> 5, lane = o & 31;
        float s0 = m0 * m0, s1 = m1 * m1;
        #pragma unroll
        for (int off = 16; off; off >>= 1) {
            s0 += __shfl_down_sync(0xffffffffu, s0, off);
            s1 += __shfl_down_sync(0xffffffffu, s1, off);
        }
        if (lane == 0) { r0[w] = s0; r1[w] = s1; }
        __syncthreads();
        if (o == 0) {
            float t0 = 0.f, t1 = 0.f;
            #pragma unroll
            for (int i = 0; i < O / 32; i++) { t0 += r0[i]; t1 += r1[i]; }
            d_xx[p0] = t0;
            d_xx[p0 + 1] = t1;
        }
    }
}

// ---------------- concat + W5 + bn/lrelu + max over N (per batch), f32x2 ----------------
__global__ void fuse_kernel(const float* __restrict__ g5, const float* __restrict__ b5) {
    int b = blockIdx.y;
    int n0 = blockIdx.x * 16;
    int t = threadIdx.x;                 // 256 threads
    __shared__ __align__(16) float xc[512][18];   // [channel][point], padded stride
    for (int e = t; e < 16 * 512; e += 256) {
        int pp = e >> 9, c = e & 511;
        int p = b * NPTS + n0 + pp;
        float v;
        if      (c < 64)  v = d_x1[(size_t)p * 64  + c];
        else if (c < 128) v = d_x2[(size_t)p * 64  + (c - 64)];
        else if (c < 256) v = d_x3[(size_t)p * 128 + (c - 128)];
        else              v = d_x4[(size_t)p * 256 + (c - 256)];
        xc[c][pp] = v;
    }
    __syncthreads();

    u64 a0[8], a1[8];
    #pragma unroll
    for (int q = 0; q < 8; q++) { a0[q] = 0ull; a1[q] = 0ull; }
    int o0 = t, o1 = t + 256;
    #pragma unroll 2
    for (int c = 0; c < 512; c++) {
        float w0 = d_W5t[c * 512 + o0];
        float w1 = d_W5t[c * 512 + o1];
        u64 w02 = pack2(w0, w0);
        u64 w12 = pack2(w1, w1);
        #pragma unroll
        for (int q = 0; q < 8; q++) {
            u64 xv = *(const u64*)&xc[c][2 * q];
            a0[q] = fma2(xv, w02, a0[q]);
            a1[q] = fma2(xv, w12, a1[q]);
        }
    }
    float s0 = g5[o0] * rsqrtf(1.f + 1e-5f), s1 = g5[o1] * rsqrtf(1.f + 1e-5f);
    float c0 = b5[o0], c1 = b5[o1];
    float m0 = NEGINF, m1 = NEGINF;
    #pragma unroll
    for (int q = 0; q < 8; q++) {
        float2 v0 = unpack2(a0[q]);
        float2 v1 = unpack2(a1[q]);
        float h;
        h = v0.x * s0 + c0; h = (h >= 0.f) ? h : 0.2f * h; m0 = fmaxf(m0, h);
        h = v0.y * s0 + c0; h = (h >= 0.f) ? h : 0.2f * h; m0 = fmaxf(m0, h);
        h = v1.x * s1 + c1; h = (h >= 0.f) ? h : 0.2f * h; m1 = fmaxf(m1, h);
        h = v1.y * s1 + c1; h = (h >= 0.f) ? h : 0.2f * h; m1 = fmaxf(m1, h);
    }
    atomicMaxFloat(&d_h5[b * 512 + o0], m0);
    atomicMaxFloat(&d_h5[b * 512 + o1], m1);
}

// ---------------- final: feat copy + embedding GEMV ----------------
__global__ void final_kernel(const float* __restrict__ Wemb, float* __restrict__ out) {
    int b = blockIdx.x;
    int t = threadIdx.x;                 // 512 threads
    __shared__ float h[512];
    float v = d_h5[b * 512 + t];
    h[t] = v;
    out[b * 512 + t] = v;                // feat (8,1,512)
    __syncthreads();
    if (t < 256) {
        float s = 0.f;
        #pragma unroll 4
        for (int c = 0; c < 512; c++) s += h[c] * Wemb[t * 512 + c];
        out[BATCH * 512 + b * 256 + t] = s;   // embedding (8,256)
    }
}

// ---------------- launch ----------------
extern "C" void kernel_launch(void* const* d_in, const int* in_sizes, int n_in,
                              void* d_out, int out_size) {
    const float* x    = (const float*)d_in[0];
    const float* W1   = (const float*)d_in[1];
    const float* g1   = (const float*)d_in[2];
    const float* b1   = (const float*)d_in[3];
    const float* W2   = (const float*)d_in[4];
    const float* g2   = (const float*)d_in[5];
    const float* b2   = (const float*)d_in[6];
    const float* W3   = (const float*)d_in[7];
    const float* g3   = (const float*)d_in[8];
    const float* b3   = (const float*)d_in[9];
    const float* W4   = (const float*)d_in[10];
    const float* g4   = (const float*)d_in[11];
    const float* b4   = (const float*)d_in[12];
    const float* W5   = (const float*)d_in[13];
    const float* g5   = (const float*)d_in[14];
    const float* b5   = (const float*)d_in[15];
    const float* Wemb = (const float*)d_in[16];
    float* out = (float*)d_out;

    float *px1, *px2, *px3, *px4;
    u64 *pWp1d, *pWp1c, *pWp2d, *pWp2c, *pWp3d, *pWp3c, *pWp4d, *pWp4c;
    cudaGetSymbolAddress((void**)&px1, d_x1);
    cudaGetSymbolAddress((void**)&px2, d_x2);
    cudaGetSymbolAddress((void**)&px3, d_x3);
    cudaGetSymbolAddress((void**)&px4, d_x4);
    cudaGetSymbolAddress((void**)&pWp1d, d_Wp1d);
    cudaGetSymbolAddress((void**)&pWp1c, d_Wp1c);
    cudaGetSymbolAddress((void**)&pWp2d, d_Wp2d);
    cudaGetSymbolAddress((void**)&pWp2c, d_Wp2c);
    cudaGetSymbolAddress((void**)&pWp3d, d_Wp3d);
    cudaGetSymbolAddress((void**)&pWp3c, d_Wp3c);
    cudaGetSymbolAddress((void**)&pWp4d, d_Wp4d);
    cudaGetSymbolAddress((void**)&pWp4c, d_Wp4c);

    // launch 0: all prep (packs + W5 transpose + h5 init)
    prep_kernel<<<512, 256>>>(W1, W2, W3, W4, W5);

    dim3 dg(NPTS / 64, NPTS / 64, BATCH);
    int nrows = BATCH * NPTS;            // 16384
    int nblk2 = nrows / 2;               // 8192 (2 points per edge block)

    // Layer 1: C=3 -> O=64                      (launches 1-4)
    norms_kernel<<<nrows / 4, 128>>>(x, 3);
    dist_kernel<3><<<dg, 256>>>(x);
    topk_kernel<<<nrows / 4, 128>>>();
    edge_kernel<3, 4, 64, true><<<nblk2, 64>>>(x, pWp1d, pWp1c, g1, b1, px1);

    // Layer 2: C=64 -> O=64                     (launches 5-7; ncu -s 5 captures dist2)
    dist_kernel<64><<<dg, 256>>>(px1);
    topk_kernel<<<nrows / 4, 128>>>();
    edge_kernel<64, 64, 64, true><<<nblk2, 64>>>(px1, pWp2d, pWp2c, g2, b2, px2);

    // Layer 3: C=64 -> O=128
    dist_kernel<64><<<dg, 256>>>(px2);
    topk_kernel<<<nrows / 4, 128>>>();
    edge_kernel<64, 64, 128, true><<<nblk2, 128>>>(px2, pWp3d, pWp3c, g3, b3, px3);

    // Layer 4: C=128 -> O=256
    dist_kernel<128><<<dg, 256>>>(px3);
    topk_kernel<<<nrows / 4, 128>>>();
    edge_kernel<128, 128, 256, false><<<nblk2, 256>>>(px3, pWp4d, pWp4c, g4, b4, px4);

    // Final fuse + reductions
    fuse_kernel<<<dim3(NPTS / 16, BATCH), 256>>>(g5, b5);
    final_kernel<<<BATCH, 512>>>(Wemb, out);
}